// round 4
// baseline (speedup 1.0000x reference)
#include <cuda_runtime.h>
#include <cuda_bf16.h>

#define NTHREADS 256
#define NBLOCKS  1184
#define LVL      64

// Quantize/dequantize (AdaptedEntropyModel):
//   r = x - means
//   pos = clip(searchsorted(cb, r, side='left'), 1, 63)
//   sym = (r - cb[pos-1] <= cb[pos] - r) ? pos-1 : pos
//   y_hat = cb[sym] + means
// Output buffer (out_size == 2N floats): [0..N) = float(sym), [N..2N) = y_hat.
//
// Search strategy: 6-step branchless lower_bound. Steps 32/16/8 probe
// register-resident codebook values (indices 31; 15/47; 7/23/39/55).
// Steps 4/2/1 probe a lane-replicated shared codebook (conflict-free).
// left/right neighbors are recovered from the probe history (last true
// probe == cb[pos-1], last false probe == cb[pos]), eliminating the two
// trailing LDS per element. Net: 3 LDS/elem instead of 8.
__global__ void __launch_bounds__(NTHREADS, 6)
quant_dequant_kernel(const float4* __restrict__ x4,
                     const float4* __restrict__ m4,
                     const float*  __restrict__ cb,
                     float* __restrict__ out_sym,
                     float* __restrict__ out_y,
                     int n4, int n)
{
    // Lane-private codebook replicas: entry i for lane l at s_cb[i*32 + l].
    __shared__ float s_cb[LVL * 32];
    for (int i = threadIdx.x; i < LVL * 32; i += NTHREADS)
        s_cb[i] = cb[i >> 5];

    // Register-resident probe values for the first 3 search levels + edges.
    const float cb0  = __ldg(cb + 0);
    const float cb1  = __ldg(cb + 1);
    const float cb7  = __ldg(cb + 7);
    const float cb15 = __ldg(cb + 15);
    const float cb23 = __ldg(cb + 23);
    const float cb31 = __ldg(cb + 31);
    const float cb39 = __ldg(cb + 39);
    const float cb47 = __ldg(cb + 47);
    const float cb55 = __ldg(cb + 55);
    const float cb63 = __ldg(cb + 63);
    __syncthreads();

    const int    lane = threadIdx.x & 31;
    const float* mycb = s_cb + lane;           // mycb[idx*32] == cb[idx]

    const int stride = gridDim.x * NTHREADS;

    for (int i = blockIdx.x * NTHREADS + threadIdx.x; i < n4; i += stride) {
        float4 xv = x4[i];
        float4 mv = m4[i];

        float r[4]  = { xv.x - mv.x, xv.y - mv.y, xv.z - mv.z, xv.w - mv.w };
        float mn[4] = { mv.x, mv.y, mv.z, mv.w };
        float sy[4], yy[4];

        #pragma unroll
        for (int j = 0; j < 4; ++j) {
            const float rv = r[j];
            int   pos = 0;
            float lv  = cb0;    // last true-probe value  -> cb[pos-1]
            float rb  = cb63;   // last false-probe value -> cb[pos]

            // step 32: probe index 31
            bool t1 = (cb31 < rv);
            if (t1) { pos = 32; lv = cb31; } else { rb = cb31; }
            // step 16: probe index pos+15 in {15, 47}
            float p16 = t1 ? cb47 : cb15;
            bool t2 = (p16 < rv);
            if (t2) { pos += 16; lv = p16; } else { rb = p16; }
            // step 8: probe index pos+7 in {7, 23, 39, 55}
            float pa = t1 ? cb39 : cb7;
            float pb = t1 ? cb55 : cb23;
            float p8 = t2 ? pb : pa;
            if (p8 < rv) { pos += 8; lv = p8; } else { rb = p8; }
            // steps 4, 2, 1: shared probes
            #pragma unroll
            for (int step = 4; step > 0; step >>= 1) {
                float p = mycb[(pos + step - 1) << 5];
                if (p < rv) { pos += step; lv = p; } else { rb = p; }
            }
            // pos == 0 => clip to 1: neighbors are cb[0], cb[1]
            if (pos == 0) { pos = 1; lv = cb0; rb = cb1; }

            // Exact tie rule from the reference, same fp32 ops.
            bool take_left = (rv - lv) <= (rb - rv);
            sy[j] = (float)(take_left ? (pos - 1) : pos);
            yy[j] = (take_left ? lv : rb) + mn[j];
        }

        ((float4*)out_sym)[i] = make_float4(sy[0], sy[1], sy[2], sy[3]);
        ((float4*)out_y)[i]   = make_float4(yy[0], yy[1], yy[2], yy[3]);
    }

    // Scalar tail (n not divisible by 4 — not expected here, but safe).
    int tail_start = n4 * 4;
    for (int i = tail_start + blockIdx.x * NTHREADS + threadIdx.x; i < n; i += stride) {
        const float* xs = (const float*)x4;
        const float* ms = (const float*)m4;
        float mvs = ms[i];
        float rv  = xs[i] - mvs;
        int pos = 0;
        float lv = cb0, rb = cb63;
        #pragma unroll
        for (int step = 32; step > 0; step >>= 1) {
            float p = mycb[(pos + step - 1) << 5];
            if (p < rv) { pos += step; lv = p; } else { rb = p; }
        }
        if (pos == 0) { pos = 1; lv = cb0; rb = cb1; }
        bool take_left = (rv - lv) <= (rb - rv);
        out_sym[i] = (float)(take_left ? (pos - 1) : pos);
        out_y[i]   = (take_left ? lv : rb) + mvs;
    }
}

extern "C" void kernel_launch(void* const* d_in, const int* in_sizes, int n_in,
                              void* d_out, int out_size)
{
    const float* x     = (const float*)d_in[0];   // [B,C,H,W] f32
    const float* means = (const float*)d_in[1];   // [B,C,H,W] f32
    const float* cb    = (const float*)d_in[2];   // [64] f32 sorted

    int n  = in_sizes[0];
    int n4 = n >> 2;

    float* out_sym = (float*)d_out;       // first N floats: symbols (exact in f32)
    float* out_y   = out_sym + n;         // next  N floats: y_hat

    quant_dequant_kernel<<<NBLOCKS, NTHREADS>>>(
        (const float4*)x, (const float4*)means, cb, out_sym, out_y, n4, n);
}

// round 5
// speedup vs baseline: 1.0556x; 1.0556x over previous
#include <cuda_runtime.h>
#include <cuda_bf16.h>

#define NTHREADS 256
#define MINBLK   7
#define NBLOCKS  (148 * MINBLK)
#define LVL      64

// Quantize/dequantize (AdaptedEntropyModel):
//   r = x - means
//   pos = clip(searchsorted(cb, r, side='left'), 1, 63)
//   sym = (r - cb[pos-1] <= cb[pos] - r) ? pos-1 : pos
//   y_hat = cb[sym] + means
// Output buffer (out_size == 2N floats): [0..N) = float(sym), [N..2N) = y_hat.
//
// Search: 6-step branchless lower_bound. Step 32 probes a register (cb[31]);
// steps 16/8/4/2/1 probe a lane-replicated shared codebook (conflict-free).
// left/right neighbors are recovered from the probe history (last true probe
// == cb[pos-1], last false probe == cb[pos]); pos==0 (r < cb[0]) is a rare
// divergent branch. Net: 5 LDS/elem (R2 had 8) at ~zero register cost.
__global__ void __launch_bounds__(NTHREADS, MINBLK)
quant_dequant_kernel(const float4* __restrict__ x4,
                     const float4* __restrict__ m4,
                     const float*  __restrict__ cb,
                     float* __restrict__ out_sym,
                     float* __restrict__ out_y,
                     int n4, int n)
{
    // Lane-private codebook replicas: entry i for lane l at s_cb[i*32 + l].
    __shared__ float s_cb[LVL * 32];
    for (int i = threadIdx.x; i < LVL * 32; i += NTHREADS)
        s_cb[i] = cb[i >> 5];

    const float cb0  = __ldg(cb + 0);
    const float cb31 = __ldg(cb + 31);
    const float cb63 = __ldg(cb + 63);
    __syncthreads();

    const int    lane = threadIdx.x & 31;
    const float* mycb = s_cb + lane;           // mycb[idx*32] == cb[idx]

    const int stride = gridDim.x * NTHREADS;

    for (int i = blockIdx.x * NTHREADS + threadIdx.x; i < n4; i += stride) {
        float4 xv = x4[i];
        float4 mv = m4[i];

        float r[4]  = { xv.x - mv.x, xv.y - mv.y, xv.z - mv.z, xv.w - mv.w };
        float mn[4] = { mv.x, mv.y, mv.z, mv.w };
        float sy[4], yy[4];

        #pragma unroll
        for (int j = 0; j < 4; ++j) {
            const float rv = r[j];
            int   pos = 0;
            float lv  = cb0;    // last true-probe value  -> cb[pos-1]
            float rb  = cb63;   // last false-probe value -> cb[pos]

            // step 32: probe index 31 from register
            if (cb31 < rv) { pos = 32; lv = cb31; } else { rb = cb31; }
            // steps 16..1: shared probes, invariant-maintaining
            #pragma unroll
            for (int step = 16; step > 0; step >>= 1) {
                float p = mycb[(pos + step - 1) << 5];
                if (p < rv) { pos += step; lv = p; } else { rb = p; }
            }
            // pos == 0 => clip to 1: neighbors cb[0], cb[1] (rare: r < cb[0])
            if (pos == 0) { pos = 1; lv = cb0; rb = mycb[1 << 5]; }

            // Exact tie rule from the reference, same fp32 ops.
            bool take_left = (rv - lv) <= (rb - rv);
            sy[j] = (float)(take_left ? (pos - 1) : pos);
            yy[j] = (take_left ? lv : rb) + mn[j];
        }

        ((float4*)out_sym)[i] = make_float4(sy[0], sy[1], sy[2], sy[3]);
        ((float4*)out_y)[i]   = make_float4(yy[0], yy[1], yy[2], yy[3]);
    }

    // Scalar tail (n not divisible by 4 — not expected here, but safe).
    int tail_start = n4 * 4;
    for (int i = tail_start + blockIdx.x * NTHREADS + threadIdx.x; i < n; i += stride) {
        const float* xs = (const float*)x4;
        const float* ms = (const float*)m4;
        float mvs = ms[i];
        float rv  = xs[i] - mvs;
        int pos = 0;
        float lv = cb0, rb = cb63;
        if (cb31 < rv) { pos = 32; lv = cb31; } else { rb = cb31; }
        #pragma unroll
        for (int step = 16; step > 0; step >>= 1) {
            float p = mycb[(pos + step - 1) << 5];
            if (p < rv) { pos += step; lv = p; } else { rb = p; }
        }
        if (pos == 0) { pos = 1; lv = cb0; rb = mycb[1 << 5]; }
        bool take_left = (rv - lv) <= (rb - rv);
        out_sym[i] = (float)(take_left ? (pos - 1) : pos);
        out_y[i]   = (take_left ? lv : rb) + mvs;
    }
}

extern "C" void kernel_launch(void* const* d_in, const int* in_sizes, int n_in,
                              void* d_out, int out_size)
{
    const float* x     = (const float*)d_in[0];   // [B,C,H,W] f32
    const float* means = (const float*)d_in[1];   // [B,C,H,W] f32
    const float* cb    = (const float*)d_in[2];   // [64] f32 sorted

    int n  = in_sizes[0];
    int n4 = n >> 2;

    float* out_sym = (float*)d_out;       // first N floats: symbols (exact in f32)
    float* out_y   = out_sym + n;         // next  N floats: y_hat

    quant_dequant_kernel<<<NBLOCKS, NTHREADS>>>(
        (const float4*)x, (const float4*)means, cb, out_sym, out_y, n4, n);
}

// round 6
// speedup vs baseline: 1.0671x; 1.0109x over previous
#include <cuda_runtime.h>
#include <cuda_bf16.h>

#define NTHREADS 256
#define MINBLK   6
#define NBLOCKS  (148 * MINBLK)
#define LVL      64

// Quantize/dequantize (AdaptedEntropyModel):
//   r = x - means
//   pos = clip(searchsorted(cb, r, side='left'), 1, 63)
//   sym = (r - cb[pos-1] <= cb[pos] - r) ? pos-1 : pos
//   y_hat = cb[sym] + means
// Output (out_size == 2N floats): [0..N) = float(sym), [N..2N) = y_hat.
//
// R5: R2's cheap search body (probes + 2 neighbor LDS, minimal ALU),
// cb[31] register probe, and a 2-stage software pipeline so the next
// iteration's LDG.128s overlap the current iteration's compute+LDS chain.

__device__ __forceinline__ void process4(float4 xv, float4 mv,
                                         const float* __restrict__ mycb,
                                         float cb31,
                                         float4& so, float4& yo)
{
    float r[4]  = { xv.x - mv.x, xv.y - mv.y, xv.z - mv.z, xv.w - mv.w };
    float mn[4] = { mv.x, mv.y, mv.z, mv.w };
    float sy[4], yy[4];

    #pragma unroll
    for (int j = 0; j < 4; ++j) {
        const float rv = r[j];
        // Branchless lower_bound over 64 sorted entries (6 steps);
        // first probe (index 31) from a register.
        int pos = (cb31 < rv) ? 32 : 0;
        #pragma unroll
        for (int step = 16; step > 0; step >>= 1) {
            if (mycb[(pos + step - 1) << 5] < rv) pos += step;
        }
        pos = min(max(pos, 1), LVL - 1);       // clip to [1,63] like reference
        float left  = mycb[(pos - 1) << 5];
        float right = mycb[pos << 5];
        // Exact tie rule from the reference, same fp32 ops.
        bool take_left = (rv - left) <= (right - rv);
        sy[j] = (float)(take_left ? (pos - 1) : pos);
        yy[j] = (take_left ? left : right) + mn[j];
    }
    so = make_float4(sy[0], sy[1], sy[2], sy[3]);
    yo = make_float4(yy[0], yy[1], yy[2], yy[3]);
}

__global__ void __launch_bounds__(NTHREADS, MINBLK)
quant_dequant_kernel(const float4* __restrict__ x4,
                     const float4* __restrict__ m4,
                     const float*  __restrict__ cb,
                     float* __restrict__ out_sym,
                     float* __restrict__ out_y,
                     int n4, int n)
{
    // Lane-private codebook replicas: entry i for lane l at s_cb[i*32 + l] ->
    // every data-dependent probe hits bank == lane (conflict-free).
    __shared__ float s_cb[LVL * 32];
    for (int i = threadIdx.x; i < LVL * 32; i += NTHREADS)
        s_cb[i] = cb[i >> 5];
    const float cb31 = __ldg(cb + 31);
    __syncthreads();

    const int    lane = threadIdx.x & 31;
    const float* mycb = s_cb + lane;           // mycb[idx*32] == cb[idx]

    const int stride = gridDim.x * NTHREADS;
    int i = blockIdx.x * NTHREADS + threadIdx.x;

    if (i < n4) {
        // 2-stage pipeline: loads for iteration k+1 issue before the
        // compute/LDS chain of iteration k.
        float4 xv = x4[i];
        float4 mv = m4[i];
        int inext = i + stride;
        while (inext < n4) {
            float4 xn = x4[inext];
            float4 mn_ = m4[inext];
            float4 so, yo;
            process4(xv, mv, mycb, cb31, so, yo);
            ((float4*)out_sym)[i] = so;
            ((float4*)out_y)[i]   = yo;
            i = inext; inext += stride;
            xv = xn; mv = mn_;
        }
        float4 so, yo;
        process4(xv, mv, mycb, cb31, so, yo);
        ((float4*)out_sym)[i] = so;
        ((float4*)out_y)[i]   = yo;
    }

    // Scalar tail (n not divisible by 4 — not expected here, but safe).
    int tail_start = n4 * 4;
    for (int t = tail_start + blockIdx.x * NTHREADS + threadIdx.x; t < n; t += stride) {
        const float* xs = (const float*)x4;
        const float* ms = (const float*)m4;
        float mvs = ms[t];
        float rv  = xs[t] - mvs;
        int pos = (cb31 < rv) ? 32 : 0;
        #pragma unroll
        for (int step = 16; step > 0; step >>= 1) {
            if (mycb[(pos + step - 1) << 5] < rv) pos += step;
        }
        pos = min(max(pos, 1), LVL - 1);
        float left  = mycb[(pos - 1) << 5];
        float right = mycb[pos << 5];
        bool take_left = (rv - left) <= (right - rv);
        out_sym[t] = (float)(take_left ? (pos - 1) : pos);
        out_y[t]   = (take_left ? left : right) + mvs;
    }
}

extern "C" void kernel_launch(void* const* d_in, const int* in_sizes, int n_in,
                              void* d_out, int out_size)
{
    const float* x     = (const float*)d_in[0];   // [B,C,H,W] f32
    const float* means = (const float*)d_in[1];   // [B,C,H,W] f32
    const float* cb    = (const float*)d_in[2];   // [64] f32 sorted

    int n  = in_sizes[0];
    int n4 = n >> 2;

    float* out_sym = (float*)d_out;       // first N floats: symbols (exact in f32)
    float* out_y   = out_sym + n;         // next  N floats: y_hat

    quant_dequant_kernel<<<NBLOCKS, NTHREADS>>>(
        (const float4*)x, (const float4*)means, cb, out_sym, out_y, n4, n);
}